// round 7
// baseline (speedup 1.0000x reference)
#include <cuda_runtime.h>
#include <math.h>
#include <stdint.h>

#define BB    8
#define N1    2048
#define N2    8192
#define C1    256
#define C2    128
#define CIN   384
#define MOUT  256
#define NTOT  (BB*N2)      // 65536 columns
#define BNCOL 64           // GEMM block N
#define NBLK  (NTOT/BNCOL) // 1024 GEMM blocks

// pipeline geometry
#define PSTAGES   4
#define XROW      72                           // X row stride (words)
#define W_STAGE   (256*20*4)                   // 20480 B
#define X_STAGE   (16*XROW*4)                  // 4608 B
#define WOFF      0
#define XOFF      (PSTAGES*W_STAGE)
#define SCOFF     (XOFF + PSTAGES*X_STAGE)
#define SMEM_DYN  (SCOFF + 2*256*4)            // ~102.4 KB

// ---------------- scratch (static __device__; no allocation) ----------------
__device__ int    g_idx[BB*N2*3];
__device__ float  g_wgt[BB*N2*3];
__device__ float  g_interp[(size_t)BB*C1*N2];   // 67 MB
__device__ float  g_Y1[(size_t)BB*MOUT*N2];     // 67 MB
__device__ float  g_scale1[MOUT], g_shift1[MOUT];
__device__ float  g_scale2[MOUT], g_shift2[MOUT];
__device__ float2 g_bpart[(size_t)NBLK*MOUT];   // per-block {sum,sumsq}

__device__ __forceinline__ float tf32_trunc(float x) {
    return __int_as_float(__float_as_int(x) & 0xffffe000);
}

// ---------------- 1) three_nn ------------------------------------------------
__global__ void knn_kernel(const float* __restrict__ xyz2,
                           const float* __restrict__ xyz1)
{
    __shared__ float sx[N1], sy[N1], sz[N1];
    const int b = blockIdx.y;
    const float* p1 = xyz1 + (size_t)b * 3 * N1;
    for (int t = threadIdx.x; t < N1; t += blockDim.x) {
        sx[t] = p1[t];
        sy[t] = p1[N1 + t];
        sz[t] = p1[2*N1 + t];
    }
    __syncthreads();

    const int n = blockIdx.x * blockDim.x + threadIdx.x;
    const float* p2 = xyz2 + (size_t)b * 3 * N2;
    const float px = p2[n], py = p2[N2 + n], pz = p2[2*N2 + n];

    float d0 = 3.4e38f, d1 = 3.4e38f, d2v = 3.4e38f;
    int   i0 = 0, i1 = 0, i2 = 0;
    #pragma unroll 4
    for (int j = 0; j < N1; ++j) {
        float dx = px - sx[j];
        float dy = py - sy[j];
        float dz = pz - sz[j];
        float d = dx*dx + dy*dy + dz*dz;
        if (d < d2v) {
            if (d < d1) {
                d2v = d1; i2 = i1;
                if (d < d0) { d1 = d0; i1 = i0; d0 = d; i0 = j; }
                else        { d1 = d;  i1 = j; }
            } else { d2v = d; i2 = j; }
        }
    }
    d0  = fmaxf(d0,  1e-10f);
    d1  = fmaxf(d1,  1e-10f);
    d2v = fmaxf(d2v, 1e-10f);
    float r0 = 1.0f / d0, r1 = 1.0f / d1, r2 = 1.0f / d2v;
    float inv = 1.0f / (r0 + r1 + r2);
    size_t base = ((size_t)b * N2 + n) * 3;
    g_idx[base]   = i0; g_idx[base+1] = i1; g_idx[base+2] = i2;
    g_wgt[base]   = r0*inv; g_wgt[base+1] = r1*inv; g_wgt[base+2] = r2*inv;
}

// ---------------- 2) weighted gather -> g_interp ----------------------------
__global__ void interp_kernel(const float* __restrict__ feat1)
{
    const int b = blockIdx.y;
    const int n = blockIdx.x * blockDim.x + threadIdx.x;
    size_t base = ((size_t)b * N2 + n) * 3;
    const int   i0 = g_idx[base], i1 = g_idx[base+1], i2 = g_idx[base+2];
    const float w0 = g_wgt[base], w1 = g_wgt[base+1], w2 = g_wgt[base+2];
    const float* f1 = feat1 + (size_t)b * C1 * N1;
    float* X = g_interp + (size_t)b * C1 * N2 + n;
    #pragma unroll 4
    for (int c = 0; c < C1; ++c) {
        const float* row = f1 + c * N1;
        X[(size_t)c * N2] = w0 * row[i0] + w1 * row[i1] + w2 * row[i2];
    }
}

// ---------------- mma / ldmatrix / cp.async wrappers ------------------------
__device__ __forceinline__ void mma_tf32(float* d, const uint32_t* a, const uint32_t* b)
{
    asm volatile(
        "mma.sync.aligned.m16n8k8.row.col.f32.tf32.tf32.f32 "
        "{%0,%1,%2,%3}, {%4,%5,%6,%7}, {%8,%9}, {%0,%1,%2,%3};\n"
        : "+f"(d[0]), "+f"(d[1]), "+f"(d[2]), "+f"(d[3])
        : "r"(a[0]), "r"(a[1]), "r"(a[2]), "r"(a[3]),
          "r"(b[0]), "r"(b[1]));
}

__device__ __forceinline__ void ldsm_x4(uint32_t* r, uint32_t saddr)
{
    asm volatile(
        "ldmatrix.sync.aligned.m8n8.x4.shared.b16 {%0,%1,%2,%3}, [%4];\n"
        : "=r"(r[0]), "=r"(r[1]), "=r"(r[2]), "=r"(r[3])
        : "r"(saddr));
}

__device__ __forceinline__ void cp_async16(uint32_t dst, const void* src)
{
    asm volatile("cp.async.cg.shared.global [%0], [%1], 16;\n"
                 :: "r"(dst), "l"(src));
}
__device__ __forceinline__ void cp_commit()
{
    asm volatile("cp.async.commit_group;\n");
}
template<int N>
__device__ __forceinline__ void cp_wait()
{
    asm volatile("cp.async.wait_group %0;\n" :: "n"(N));
}

// ---------------- 3/5) tensor-core GEMM, 3xTF32, 4-stage, 1 barrier/iter ----
// out[b,m,n2] = sum_k W[m,k]*X[k,(b,n2)] + bias[m]; W original [M][K] layout.
// CONCAT: X rows [0,C1) from A1 (g_interp), rest from A2 (feat2).
// FUSE:   X element -> relu(x*scale[k]+shift[k]) applied at b-fragment read.
// Emits per-block per-channel {sum,sumsq} into bpart (fused BN stats).
template<int K, bool CONCAT, bool FUSE>
__global__ void __launch_bounds__(512, 2)
gemm_tc_kernel(const float* __restrict__ W, const float* __restrict__ bias,
               const float* __restrict__ A1, const float* __restrict__ A2,
               const float* __restrict__ scale, const float* __restrict__ shift,
               float* __restrict__ out, float2* __restrict__ bpart)
{
    extern __shared__ char sm[];
    const uint32_t smb = (uint32_t)__cvta_generic_to_shared(sm);
    const uint32_t wsm = smb + WOFF;
    const uint32_t xsm = smb + XOFF;
    float* s_sc = (float*)(sm + SCOFF);
    float* s_sh = (float*)(sm + SCOFF + 256*4);

    const int tid   = threadIdx.x;
    const int lane  = tid & 31;
    const int wid   = tid >> 5;         // 0..15
    const int g     = lane >> 2;
    const int tig   = lane & 3;
    const int mwarp = wid >> 1;         // 0..7 -> m base mwarp*32
    const int nwarp = wid & 1;          // 0..1 -> n base nwarp*32

    const int nglob = blockIdx.x * BNCOL;
    const int b     = nglob >> 13;
    const int n2    = nglob & (N2 - 1);

    const float* A1b = A1 + (size_t)b * (CONCAT ? C1 : K) * N2 + n2;
    const float* A2b = CONCAT ? (A2 + (size_t)b * C2 * N2 + n2) : nullptr;

    if (FUSE && tid < K) {
        s_sc[tid] = scale[tid];
        s_sh[tid] = shift[tid];
    }

    float acc[2][4][4];
    #pragma unroll
    for (int mt = 0; mt < 2; ++mt)
        #pragma unroll
        for (int nt = 0; nt < 4; ++nt)
            #pragma unroll
            for (int r = 0; r < 4; ++r) acc[mt][nt][r] = 0.0f;

    // ldmatrix lane address within a W stage
    const int rowoff  = ((lane >> 3) & 1) * 8 + (lane & 7);
    const int wordoff = (lane >> 4) * 4;
    const uint32_t aOff = ((((mwarp*32 + rowoff) * 20) + wordoff) << 2);

    // loader task coords
    const int xkr = tid >> 4;           // X: k row (tid<256)
    const int xn4 = (tid & 15) * 4;     //    n quad

    auto load_stage = [&](int k0, int stg) {
        // W tile: 256 m x 16 k, 2 tasks/thread
        const uint32_t wdst = wsm + stg * W_STAGE;
        #pragma unroll
        for (int q = 0; q < 2; ++q) {
            const int t  = tid + q * 512;
            const int m  = t >> 2;
            const int kc = (t & 3) * 4;
            cp_async16(wdst + (((m * 20) + kc) << 2),
                       W + (size_t)m * K + k0 + kc);
        }
        // X tile: 16 k x 64 n
        if (tid < 256) {
            const int kg = k0 + xkr;
            const float* src;
            if (CONCAT)
                src = (kg < C1) ? (A1b + (size_t)kg * N2)
                                : (A2b + (size_t)(kg - C1) * N2);
            else
                src = A1b + (size_t)kg * N2;
            cp_async16(xsm + stg * X_STAGE + (((xkr * XROW) + xn4) << 2),
                       src + xn4);
        }
    };

    constexpr int NITER = K / 16;
    #pragma unroll
    for (int p = 0; p < PSTAGES - 1; ++p) {
        load_stage(p * 16, p);
        cp_commit();
    }

    for (int i = 0; i < NITER; ++i) {
        // stage i ready (PSTAGES-2 newer groups may still be in flight)
        cp_wait<PSTAGES - 2>();
        __syncthreads();   // stage-i visible everywhere; buffer (i-1)%P reusable

        const int inext = i + PSTAGES - 1;
        if (inext < NITER) load_stage(inext * 16, inext % PSTAGES);
        cp_commit();

        const int stg = i % PSTAGES;
        const uint32_t aBase = wsm + stg * W_STAGE + aOff;
        const float* Xs = (const float*)(sm + XOFF + stg * X_STAGE);
        const int k0 = i * 16;

        #pragma unroll
        for (int ks = 0; ks < 16; ks += 8) {
            float sc0, sh0, sc1, sh1;
            if (FUSE) {
                sc0 = s_sc[k0 + ks + tig];     sh0 = s_sh[k0 + ks + tig];
                sc1 = s_sc[k0 + ks + tig + 4]; sh1 = s_sh[k0 + ks + tig + 4];
            }
            #pragma unroll
            for (int mt = 0; mt < 2; ++mt) {
                uint32_t ah[4], al[4];
                ldsm_x4(ah, aBase + ((mt * 16 * 20 + ks) << 2));
                #pragma unroll
                for (int j = 0; j < 4; ++j) {
                    const float a = __uint_as_float(ah[j]);
                    al[j] = __float_as_uint(a - tf32_trunc(a));
                }
                #pragma unroll
                for (int nt = 0; nt < 4; ++nt) {
                    const int nn = nwarp * 32 + nt * 8 + g;
                    float b0 = Xs[(ks + tig) * XROW + nn];
                    float b1 = Xs[(ks + tig + 4) * XROW + nn];
                    if (FUSE) {
                        b0 = fmaxf(fmaf(b0, sc0, sh0), 0.0f);
                        b1 = fmaxf(fmaf(b1, sc1, sh1), 0.0f);
                    }
                    uint32_t bh[2] = { __float_as_uint(b0), __float_as_uint(b1) };
                    uint32_t bl[2] = { __float_as_uint(b0 - tf32_trunc(b0)),
                                       __float_as_uint(b1 - tf32_trunc(b1)) };
                    mma_tf32(acc[mt][nt], ah, bh);   // hi*hi
                    mma_tf32(acc[mt][nt], ah, bl);   // hi*lo
                    mma_tf32(acc[mt][nt], al, bh);   // lo*hi
                }
            }
        }
    }
    __syncthreads();   // protect smem reuse below (W stage may be last stage)

    // ---- epilogue: bias add, store, fused per-channel stats ----
    float* part = (float*)sm;   // reuse W stage 0: [nwarp][256][{s,ss}]
    float* ob = out + (size_t)b * MOUT * N2 + n2;
    #pragma unroll
    for (int mt = 0; mt < 2; ++mt) {
        #pragma unroll
        for (int h = 0; h < 2; ++h) {
            const int m  = mwarp * 32 + mt * 16 + h * 8 + g;
            const float bv = bias[m];
            float s = 0.0f, ss = 0.0f;
            #pragma unroll
            for (int nt = 0; nt < 4; ++nt) {
                const float v0 = acc[mt][nt][h*2+0] + bv;
                const float v1 = acc[mt][nt][h*2+1] + bv;
                const int n = nwarp * 32 + nt * 8 + 2 * tig;
                *(float2*)(ob + (size_t)m * N2 + n) = make_float2(v0, v1);
                s  += v0 + v1;
                ss += v0*v0 + v1*v1;
            }
            s  += __shfl_xor_sync(0xffffffffu, s, 1);
            s  += __shfl_xor_sync(0xffffffffu, s, 2);
            ss += __shfl_xor_sync(0xffffffffu, ss, 1);
            ss += __shfl_xor_sync(0xffffffffu, ss, 2);
            if (tig == 0) {
                part[(nwarp * 256 + m) * 2 + 0] = s;
                part[(nwarp * 256 + m) * 2 + 1] = ss;
            }
        }
    }
    __syncthreads();
    if (tid < 256) {
        float2 r;
        r.x = part[tid * 2]     + part[(256 + tid) * 2];
        r.y = part[tid * 2 + 1] + part[(256 + tid) * 2 + 1];
        bpart[(size_t)blockIdx.x * MOUT + tid] = r;
    }
}

// ---------------- 4/6) stage-2 stats reduce ---------------------------------
__global__ void stats2_kernel(const float* __restrict__ gamma,
                              const float* __restrict__ beta,
                              float* __restrict__ scale,
                              float* __restrict__ shift)
{
    const int c = blockIdx.x;
    double s = 0.0, ss = 0.0;
    for (int j = threadIdx.x; j < NBLK; j += 256) {
        const float2 p = g_bpart[(size_t)j * MOUT + c];
        s  += (double)p.x;
        ss += (double)p.y;
    }
    __shared__ double rs[256], rss[256];
    rs[threadIdx.x] = s; rss[threadIdx.x] = ss;
    __syncthreads();
    for (int o = 128; o > 0; o >>= 1) {
        if (threadIdx.x < o) {
            rs[threadIdx.x]  += rs[threadIdx.x + o];
            rss[threadIdx.x] += rss[threadIdx.x + o];
        }
        __syncthreads();
    }
    if (threadIdx.x == 0) {
        const double mean = rs[0] / (double)NTOT;
        const double var  = rss[0] / (double)NTOT - mean * mean;
        const float istd  = (float)(1.0 / sqrt(var + 1e-3));
        const float sc    = gamma[c] * istd;
        scale[c] = sc;
        shift[c] = beta[c] - (float)mean * sc;
    }
}

// ---------------- 7) in-place BN+ReLU of layer-2 output ---------------------
__global__ void finalize_kernel(float* __restrict__ out)
{
    const size_t i4 = (size_t)blockIdx.x * blockDim.x + threadIdx.x;
    const int c = (int)((i4 >> 11) & 255);
    float4* p = (float4*)out + i4;
    float4 v = *p;
    const float sc = g_scale2[c], sh = g_shift2[c];
    v.x = fmaxf(fmaf(v.x, sc, sh), 0.0f);
    v.y = fmaxf(fmaf(v.y, sc, sh), 0.0f);
    v.z = fmaxf(fmaf(v.z, sc, sh), 0.0f);
    v.w = fmaxf(fmaf(v.w, sc, sh), 0.0f);
    *p = v;
}

// ---------------- launch ----------------------------------------------------
extern "C" void kernel_launch(void* const* d_in, const int* in_sizes, int n_in,
                              void* d_out, int out_size)
{
    const float* xyz2  = (const float*)d_in[0];
    const float* xyz1  = (const float*)d_in[1];
    const float* feat2 = (const float*)d_in[2];
    const float* feat1 = (const float*)d_in[3];
    const float* W1    = (const float*)d_in[4];
    const float* b1    = (const float*)d_in[5];
    const float* g1    = (const float*)d_in[6];
    const float* be1   = (const float*)d_in[7];
    const float* W2    = (const float*)d_in[8];
    const float* b2    = (const float*)d_in[9];
    const float* g2    = (const float*)d_in[10];
    const float* be2   = (const float*)d_in[11];
    float* out = (float*)d_out;

    float  *p_interp, *p_Y1, *p_s1, *p_sh1, *p_s2, *p_sh2;
    float2 *p_bpart;
    cudaGetSymbolAddress((void**)&p_interp, g_interp);
    cudaGetSymbolAddress((void**)&p_Y1,     g_Y1);
    cudaGetSymbolAddress((void**)&p_s1,     g_scale1);
    cudaGetSymbolAddress((void**)&p_sh1,    g_shift1);
    cudaGetSymbolAddress((void**)&p_s2,     g_scale2);
    cudaGetSymbolAddress((void**)&p_sh2,    g_shift2);
    cudaGetSymbolAddress((void**)&p_bpart,  g_bpart);

    static int attr_done = 0;
    if (!attr_done) {
        cudaFuncSetAttribute(gemm_tc_kernel<CIN, true, false>,
                             cudaFuncAttributeMaxDynamicSharedMemorySize, SMEM_DYN);
        cudaFuncSetAttribute(gemm_tc_kernel<MOUT, false, true>,
                             cudaFuncAttributeMaxDynamicSharedMemorySize, SMEM_DYN);
        attr_done = 1;
    }

    knn_kernel<<<dim3(N2/256, BB), 256>>>(xyz2, xyz1);
    interp_kernel<<<dim3(N2/256, BB), 256>>>(feat1);

    // layer 1: y1 = W1 @ [interp; feat2] + b1 (raw) + fused stats partials
    gemm_tc_kernel<CIN, true, false><<<NBLK, 512, SMEM_DYN>>>(
        W1, b1, p_interp, feat2, nullptr, nullptr, p_Y1, p_bpart);
    stats2_kernel<<<MOUT, 256>>>(g1, be1, p_s1, p_sh1);

    // layer 2: y2 = W2 @ relu(bn(y1)) + b2 -> d_out (raw) + fused stats
    gemm_tc_kernel<MOUT, false, true><<<NBLK, 512, SMEM_DYN>>>(
        W2, b2, p_Y1, nullptr, p_s1, p_sh1, out, p_bpart);
    stats2_kernel<<<MOUT, 256>>>(g2, be2, p_s2, p_sh2);

    finalize_kernel<<<(NTOT * MOUT / 4) / 256, 256>>>(out);
}

// round 9
// speedup vs baseline: 1.0463x; 1.0463x over previous
#include <cuda_runtime.h>
#include <math.h>
#include <stdint.h>

#define BB    8
#define N1    2048
#define N2    8192
#define C1    256
#define C2    128
#define CIN   384
#define MOUT  256
#define NTOT  (BB*N2)      // 65536 columns
#define BNCOL 64           // GEMM block N
#define NBLK  (NTOT/BNCOL) // 1024 GEMM blocks

// pipeline geometry
#define PSTAGES   3
#define XROW      72                           // X row stride (words)
#define W_STAGE   (256*20*4)                   // 20480 B (one bulk copy)
#define X_STAGE   (16*XROW*4)                  // 4608 B
#define WOFF      0
#define XOFF      (PSTAGES*W_STAGE)            // 61440
#define SCOFF     (XOFF + PSTAGES*X_STAGE)     // 75264
#define MBOFF     (SCOFF + 2*256*4)            // 77312 (3 mbarriers)
#define SMEM_DYN  (MBOFF + 64)

#define WCH1 (CIN/16)   // 24 W chunks for GEMM1
#define WCH2 (MOUT/16)  // 16 W chunks for GEMM2

// ---------------- scratch (static __device__; no allocation) ----------------
__device__ int    g_idx[BB*N2*3];
__device__ float  g_wgt[BB*N2*3];
__device__ float  g_interp[(size_t)BB*C1*N2];   // 67 MB
__device__ float  g_Y1[(size_t)BB*MOUT*N2];     // 67 MB
__device__ float  g_scale1[MOUT], g_shift1[MOUT];
__device__ float  g_scale2[MOUT], g_shift2[MOUT];
__device__ float2 g_bpart[(size_t)NBLK*MOUT];   // per-block {sum,sumsq}
// pre-baked W smem images: per 16-k chunk, 256 rows x 20 words (pad zeroed)
__device__ __align__(128) float g_W1img[WCH1*256*20];
__device__ __align__(128) float g_W2img[WCH2*256*20];

__device__ __forceinline__ float tf32_trunc(float x) {
    return __int_as_float(__float_as_int(x) & 0xffffe000);
}

// ---------------- 1) three_nn ------------------------------------------------
__global__ void knn_kernel(const float* __restrict__ xyz2,
                           const float* __restrict__ xyz1)
{
    __shared__ float sx[N1], sy[N1], sz[N1];
    const int b = blockIdx.y;
    const float* p1 = xyz1 + (size_t)b * 3 * N1;
    for (int t = threadIdx.x; t < N1; t += blockDim.x) {
        sx[t] = p1[t];
        sy[t] = p1[N1 + t];
        sz[t] = p1[2*N1 + t];
    }
    __syncthreads();

    const int n = blockIdx.x * blockDim.x + threadIdx.x;
    const float* p2 = xyz2 + (size_t)b * 3 * N2;
    const float px = p2[n], py = p2[N2 + n], pz = p2[2*N2 + n];

    float d0 = 3.4e38f, d1 = 3.4e38f, d2v = 3.4e38f;
    int   i0 = 0, i1 = 0, i2 = 0;
    #pragma unroll 4
    for (int j = 0; j < N1; ++j) {
        float dx = px - sx[j];
        float dy = py - sy[j];
        float dz = pz - sz[j];
        float d = dx*dx + dy*dy + dz*dz;
        if (d < d2v) {
            if (d < d1) {
                d2v = d1; i2 = i1;
                if (d < d0) { d1 = d0; i1 = i0; d0 = d; i0 = j; }
                else        { d1 = d;  i1 = j; }
            } else { d2v = d; i2 = j; }
        }
    }
    d0  = fmaxf(d0,  1e-10f);
    d1  = fmaxf(d1,  1e-10f);
    d2v = fmaxf(d2v, 1e-10f);
    float r0 = 1.0f / d0, r1 = 1.0f / d1, r2 = 1.0f / d2v;
    float inv = 1.0f / (r0 + r1 + r2);
    size_t base = ((size_t)b * N2 + n) * 3;
    g_idx[base]   = i0; g_idx[base+1] = i1; g_idx[base+2] = i2;
    g_wgt[base]   = r0*inv; g_wgt[base+1] = r1*inv; g_wgt[base+2] = r2*inv;
}

// ---------------- 2) weighted gather -> g_interp ----------------------------
__global__ void interp_kernel(const float* __restrict__ feat1)
{
    const int b = blockIdx.y;
    const int n = blockIdx.x * blockDim.x + threadIdx.x;
    size_t base = ((size_t)b * N2 + n) * 3;
    const int   i0 = g_idx[base], i1 = g_idx[base+1], i2 = g_idx[base+2];
    const float w0 = g_wgt[base], w1 = g_wgt[base+1], w2 = g_wgt[base+2];
    const float* f1 = feat1 + (size_t)b * C1 * N1;
    float* X = g_interp + (size_t)b * C1 * N2 + n;
    #pragma unroll 4
    for (int c = 0; c < C1; ++c) {
        const float* row = f1 + c * N1;
        X[(size_t)c * N2] = w0 * row[i0] + w1 * row[i1] + w2 * row[i2];
    }
}

// ---------------- prep: W -> chunk-major smem images ------------------------
__global__ void prep_wimg_kernel(const float* __restrict__ W1,
                                 const float* __restrict__ W2)
{
    const int idx = blockIdx.x * blockDim.x + threadIdx.x;
    if (idx < WCH1*256*20) {
        const int c = idx / (256*20);
        const int r = idx % (256*20);
        const int m = r / 20, j = r % 20;
        g_W1img[idx] = (j < 16) ? W1[(size_t)m * CIN + c*16 + j] : 0.0f;
    }
    if (idx < WCH2*256*20) {
        const int c = idx / (256*20);
        const int r = idx % (256*20);
        const int m = r / 20, j = r % 20;
        g_W2img[idx] = (j < 16) ? W2[(size_t)m * MOUT + c*16 + j] : 0.0f;
    }
}

// ---------------- mma / ldmatrix / async wrappers ---------------------------
__device__ __forceinline__ void mma_tf32(float* d, const uint32_t* a, const uint32_t* b)
{
    asm volatile(
        "mma.sync.aligned.m16n8k8.row.col.f32.tf32.tf32.f32 "
        "{%0,%1,%2,%3}, {%4,%5,%6,%7}, {%8,%9}, {%0,%1,%2,%3};\n"
        : "+f"(d[0]), "+f"(d[1]), "+f"(d[2]), "+f"(d[3])
        : "r"(a[0]), "r"(a[1]), "r"(a[2]), "r"(a[3]),
          "r"(b[0]), "r"(b[1]));
}

__device__ __forceinline__ void ldsm_x4(uint32_t* r, uint32_t saddr)
{
    asm volatile(
        "ldmatrix.sync.aligned.m8n8.x4.shared.b16 {%0,%1,%2,%3}, [%4];\n"
        : "=r"(r[0]), "=r"(r[1]), "=r"(r[2]), "=r"(r[3])
        : "r"(saddr));
}

__device__ __forceinline__ void cp_async16(uint32_t dst, const void* src)
{
    asm volatile("cp.async.cg.shared.global [%0], [%1], 16;\n"
                 :: "r"(dst), "l"(src));
}
__device__ __forceinline__ void cp_commit()
{
    asm volatile("cp.async.commit_group;\n");
}
template<int N>
__device__ __forceinline__ void cp_wait()
{
    asm volatile("cp.async.wait_group %0;\n" :: "n"(N));
}
__device__ __forceinline__ void bulk_g2s(uint32_t dst, const void* src,
                                         uint32_t bytes, uint32_t mbar)
{
    asm volatile(
        "cp.async.bulk.shared::cluster.global.mbarrier::complete_tx::bytes "
        "[%0], [%1], %2, [%3];"
        :: "r"(dst), "l"(src), "r"(bytes), "r"(mbar) : "memory");
}
__device__ __forceinline__ void mbar_init(uint32_t mbar, uint32_t cnt)
{
    asm volatile("mbarrier.init.shared.b64 [%0], %1;" :: "r"(mbar), "r"(cnt) : "memory");
}
__device__ __forceinline__ void mbar_expect_tx(uint32_t mbar, uint32_t bytes)
{
    asm volatile("mbarrier.arrive.expect_tx.shared.b64 _, [%0], %1;"
                 :: "r"(mbar), "r"(bytes) : "memory");
}
__device__ __forceinline__ void mbar_wait(uint32_t mbar, uint32_t parity)
{
    asm volatile(
        "{\n\t.reg .pred P;\n\t"
        "W_%=:\n\t"
        "mbarrier.try_wait.parity.acquire.cta.shared::cta.b64 P, [%0], %1, 0x989680;\n\t"
        "@P bra D_%=;\n\t"
        "bra W_%=;\n\t"
        "D_%=:\n\t}"
        :: "r"(mbar), "r"(parity) : "memory");
}

// ---------------- 3/5) tensor-core GEMM, 3xTF32, bulk-W + cp.async-X --------
// out[b,m,n2] = sum_k W[m,k]*X[k,(b,n2)] + bias[m]; Wimg = pre-baked images.
// CONCAT: X rows [0,C1) from A1 (g_interp), rest from A2 (feat2).
// FUSE:   X element -> relu(x*scale[k]+shift[k]) applied at b-fragment read.
// Emits per-block per-channel {sum,sumsq} into bpart (fused BN stats).
template<int K, bool CONCAT, bool FUSE>
__global__ void __launch_bounds__(512, 2)
gemm_tc_kernel(const float* __restrict__ Wimg, const float* __restrict__ bias,
               const float* __restrict__ A1, const float* __restrict__ A2,
               const float* __restrict__ scale, const float* __restrict__ shift,
               float* __restrict__ out, float2* __restrict__ bpart)
{
    extern __shared__ char sm[];
    const uint32_t smb = (uint32_t)__cvta_generic_to_shared(sm);
    const uint32_t wsm = smb + WOFF;
    const uint32_t xsm = smb + XOFF;
    float* s_sc = (float*)(sm + SCOFF);
    float* s_sh = (float*)(sm + SCOFF + 256*4);
    const uint32_t mb0 = smb + MBOFF;   // 3 mbarriers, 8B apart

    const int tid   = threadIdx.x;
    const int lane  = tid & 31;
    const int wid   = tid >> 5;         // 0..15
    const int g     = lane >> 2;
    const int tig   = lane & 3;
    const int mwarp = wid >> 1;         // 0..7 -> m base mwarp*32
    const int nwarp = wid & 1;          // 0..1 -> n base nwarp*32

    const int nglob = blockIdx.x * BNCOL;
    const int b     = nglob >> 13;
    const int n2    = nglob & (N2 - 1);

    const float* A1b = A1 + (size_t)b * (CONCAT ? C1 : K) * N2 + n2;
    const float* A2b = CONCAT ? (A2 + (size_t)b * C2 * N2 + n2) : nullptr;

    if (FUSE && tid < K) {
        s_sc[tid] = scale[tid];
        s_sh[tid] = shift[tid];
    }
    if (tid == 0) {
        mbar_init(mb0,      1);
        mbar_init(mb0 + 8,  1);
        mbar_init(mb0 + 16, 1);
    }
    __syncthreads();   // mbarriers + s_sc visible

    float acc[2][4][4];
    #pragma unroll
    for (int mt = 0; mt < 2; ++mt)
        #pragma unroll
        for (int nt = 0; nt < 4; ++nt)
            #pragma unroll
            for (int r = 0; r < 4; ++r) acc[mt][nt][r] = 0.0f;

    // ldmatrix lane address within a W stage
    const int rowoff  = ((lane >> 3) & 1) * 8 + (lane & 7);
    const int wordoff = (lane >> 4) * 4;
    const uint32_t aOff = ((((mwarp*32 + rowoff) * 20) + wordoff) << 2);

    // X loader task coords (tid<256)
    const int xkr = tid >> 4;
    const int xn4 = (tid & 15) * 4;

    auto load_W = [&](int chunk, int stg) {        // tid==0 only
        mbar_expect_tx(mb0 + stg * 8, W_STAGE);
        bulk_g2s(wsm + stg * W_STAGE, Wimg + (size_t)chunk * (256*20),
                 W_STAGE, mb0 + stg * 8);
    };
    auto load_X = [&](int k0, int stg) {           // tid<256
        if (tid < 256) {
            const int kg = k0 + xkr;
            const float* src;
            if (CONCAT)
                src = (kg < C1) ? (A1b + (size_t)kg * N2)
                                : (A2b + (size_t)(kg - C1) * N2);
            else
                src = A1b + (size_t)kg * N2;
            cp_async16(xsm + stg * X_STAGE + (((xkr * XROW) + xn4) << 2),
                       src + xn4);
        }
    };

    constexpr int NITER = K / 16;
    #pragma unroll
    for (int p = 0; p < PSTAGES - 1; ++p) {
        if (tid == 0) load_W(p, p);
        load_X(p * 16, p);
        cp_commit();
    }

    int s = 0, ph = 0;
    for (int i = 0; i < NITER; ++i) {
        const int inext = i + PSTAGES - 1;
        const int sN = (s + PSTAGES - 1) % PSTAGES;
        // X loads issued early (R5 position — latency-hiding)
        if (inext < NITER) load_X(inext * 16, sN);
        cp_commit();
        cp_wait<PSTAGES - 2>();
        mbar_wait(mb0 + s * 8, (uint32_t)ph);
        __syncthreads();
        // W bulk for stage i+2: issued after barrier (race-free, 2 iters slack)
        if (inext < NITER && tid == 0) load_W(inext, sN);

        const uint32_t aBase = wsm + s * W_STAGE + aOff;
        const float* Xs = (const float*)(sm + XOFF + s * X_STAGE);
        const int k0 = i * 16;

        #pragma unroll
        for (int ks = 0; ks < 16; ks += 8) {
            float sc0, sh0, sc1, sh1;
            if (FUSE) {
                sc0 = s_sc[k0 + ks + tig];     sh0 = s_sh[k0 + ks + tig];
                sc1 = s_sc[k0 + ks + tig + 4]; sh1 = s_sh[k0 + ks + tig + 4];
            }
            #pragma unroll
            for (int mt = 0; mt < 2; ++mt) {
                uint32_t ah[4], al[4];
                ldsm_x4(ah, aBase + ((mt * 16 * 20 + ks) << 2));
                #pragma unroll
                for (int j = 0; j < 4; ++j) {
                    const float a = __uint_as_float(ah[j]);
                    al[j] = __float_as_uint(a - tf32_trunc(a));
                }
                #pragma unroll
                for (int nt = 0; nt < 4; ++nt) {
                    const int nn = nwarp * 32 + nt * 8 + g;
                    float b0 = Xs[(ks + tig) * XROW + nn];
                    float b1 = Xs[(ks + tig + 4) * XROW + nn];
                    if (FUSE) {
                        b0 = fmaxf(fmaf(b0, sc0, sh0), 0.0f);
                        b1 = fmaxf(fmaf(b1, sc1, sh1), 0.0f);
                    }
                    uint32_t bh[2] = { __float_as_uint(b0), __float_as_uint(b1) };
                    uint32_t bl[2] = { __float_as_uint(b0 - tf32_trunc(b0)),
                                       __float_as_uint(b1 - tf32_trunc(b1)) };
                    mma_tf32(acc[mt][nt], ah, bh);   // hi*hi
                    mma_tf32(acc[mt][nt], ah, bl);   // hi*lo
                    mma_tf32(acc[mt][nt], al, bh);   // lo*hi
                }
            }
        }
        __syncthreads();
        if (++s == PSTAGES) { s = 0; ph ^= 1; }
    }

    // ---- epilogue: bias add, store, fused per-channel stats ----
    float* part = (float*)sm;   // reuse W stage 0: [nwarp][256][{s,ss}]
    float* ob = out + (size_t)b * MOUT * N2 + n2;
    #pragma unroll
    for (int mt = 0; mt < 2; ++mt) {
        #pragma unroll
        for (int h = 0; h < 2; ++h) {
            const int m  = mwarp * 32 + mt * 16 + h * 8 + g;
            const float bv = bias[m];
            float s2 = 0.0f, ss = 0.0f;
            #pragma unroll
            for (int nt = 0; nt < 4; ++nt) {
                const float v0 = acc[mt][nt][h*2+0] + bv;
                const float v1 = acc[mt][nt][h*2+1] + bv;
                const int n = nwarp * 32 + nt * 8 + 2 * tig;
                *(float2*)(ob + (size_t)m * N2 + n) = make_float2(v0, v1);
                s2 += v0 + v1;
                ss += v0*v0 + v1*v1;
            }
            s2 += __shfl_xor_sync(0xffffffffu, s2, 1);
            s2 += __shfl_xor_sync(0xffffffffu, s2, 2);
            ss += __shfl_xor_sync(0xffffffffu, ss, 1);
            ss += __shfl_xor_sync(0xffffffffu, ss, 2);
            if (tig == 0) {
                part[(nwarp * 256 + m) * 2 + 0] = s2;
                part[(nwarp * 256 + m) * 2 + 1] = ss;
            }
        }
    }
    __syncthreads();
    if (tid < 256) {
        float2 r;
        r.x = part[tid * 2]     + part[(256 + tid) * 2];
        r.y = part[tid * 2 + 1] + part[(256 + tid) * 2 + 1];
        bpart[(size_t)blockIdx.x * MOUT + tid] = r;
    }
}

// ---------------- 4/6) stage-2 stats reduce ---------------------------------
__global__ void stats2_kernel(const float* __restrict__ gamma,
                              const float* __restrict__ beta,
                              float* __restrict__ scale,
                              float* __restrict__ shift)
{
    const int c = blockIdx.x;
    double s = 0.0, ss = 0.0;
    for (int j = threadIdx.x; j < NBLK; j += 256) {
        const float2 p = g_bpart[(size_t)j * MOUT + c];
        s  += (double)p.x;
        ss += (double)p.y;
    }
    __shared__ double rs[256], rss[256];
    rs[threadIdx.x] = s; rss[threadIdx.x] = ss;
    __syncthreads();
    for (int o = 128; o > 0; o >>= 1) {
        if (threadIdx.x < o) {
            rs[threadIdx.x]  += rs[threadIdx.x + o];
            rss[threadIdx.x] += rss[threadIdx.x + o];
        }
        __syncthreads();
    }
    if (threadIdx.x == 0) {
        const double mean = rs[0] / (double)NTOT;
        const double var  = rss[0] / (double)NTOT - mean * mean;
        const float istd  = (float)(1.0 / sqrt(var + 1e-3));
        const float sc    = gamma[c] * istd;
        scale[c] = sc;
        shift[c] = beta[c] - (float)mean * sc;
    }
}

// ---------------- 7) in-place BN+ReLU of layer-2 output ---------------------
__global__ void finalize_kernel(float* __restrict__ out)
{
    const size_t i4 = (size_t)blockIdx.x * blockDim.x + threadIdx.x;
    const int c = (int)((i4 >> 11) & 255);
    float4* p = (float4*)out + i4;
    float4 v = *p;
    const float sc = g_scale2[c], sh = g_shift2[c];
    v.x = fmaxf(fmaf(v.x, sc, sh), 0.0f);
    v.y = fmaxf(fmaf(v.y, sc, sh), 0.0f);
    v.z = fmaxf(fmaf(v.z, sc, sh), 0.0f);
    v.w = fmaxf(fmaf(v.w, sc, sh), 0.0f);
    *p = v;
}

// ---------------- launch ----------------------------------------------------
extern "C" void kernel_launch(void* const* d_in, const int* in_sizes, int n_in,
                              void* d_out, int out_size)
{
    const float* xyz2  = (const float*)d_in[0];
    const float* xyz1  = (const float*)d_in[1];
    const float* feat2 = (const float*)d_in[2];
    const float* feat1 = (const float*)d_in[3];
    const float* W1    = (const float*)d_in[4];
    const float* b1    = (const float*)d_in[5];
    const float* g1    = (const float*)d_in[6];
    const float* be1   = (const float*)d_in[7];
    const float* W2    = (const float*)d_in[8];
    const float* b2    = (const float*)d_in[9];
    const float* g2    = (const float*)d_in[10];
    const float* be2   = (const float*)d_in[11];
    float* out = (float*)d_out;

    float  *p_interp, *p_Y1, *p_s1, *p_sh1, *p_s2, *p_sh2;
    float  *p_W1img, *p_W2img;
    float2 *p_bpart;
    cudaGetSymbolAddress((void**)&p_interp, g_interp);
    cudaGetSymbolAddress((void**)&p_Y1,     g_Y1);
    cudaGetSymbolAddress((void**)&p_s1,     g_scale1);
    cudaGetSymbolAddress((void**)&p_sh1,    g_shift1);
    cudaGetSymbolAddress((void**)&p_s2,     g_scale2);
    cudaGetSymbolAddress((void**)&p_sh2,    g_shift2);
    cudaGetSymbolAddress((void**)&p_bpart,  g_bpart);
    cudaGetSymbolAddress((void**)&p_W1img,  g_W1img);
    cudaGetSymbolAddress((void**)&p_W2img,  g_W2img);

    static int attr_done = 0;
    if (!attr_done) {
        cudaFuncSetAttribute(gemm_tc_kernel<CIN, true, false>,
                             cudaFuncAttributeMaxDynamicSharedMemorySize, SMEM_DYN);
        cudaFuncSetAttribute(gemm_tc_kernel<MOUT, false, true>,
                             cudaFuncAttributeMaxDynamicSharedMemorySize, SMEM_DYN);
        attr_done = 1;
    }

    knn_kernel<<<dim3(N2/256, BB), 256>>>(xyz2, xyz1);
    interp_kernel<<<dim3(N2/256, BB), 256>>>(feat1);
    prep_wimg_kernel<<<(WCH1*256*20 + 255)/256, 256>>>(W1, W2);

    // layer 1: y1 = W1 @ [interp; feat2] + b1 (raw) + fused stats partials
    gemm_tc_kernel<CIN, true, false><<<NBLK, 512, SMEM_DYN>>>(
        p_W1img, b1, p_interp, feat2, nullptr, nullptr, p_Y1, p_bpart);
    stats2_kernel<<<MOUT, 256>>>(g1, be1, p_s1, p_sh1);

    // layer 2: y2 = W2 @ relu(bn(y1)) + b2 -> d_out (raw) + fused stats
    gemm_tc_kernel<MOUT, false, true><<<NBLK, 512, SMEM_DYN>>>(
        p_W2img, b2, p_Y1, nullptr, p_s1, p_sh1, out, p_bpart);
    stats2_kernel<<<MOUT, 256>>>(g2, be2, p_s2, p_sh2);

    finalize_kernel<<<(NTOT * MOUT / 4) / 256, 256>>>(out);
}

// round 10
// speedup vs baseline: 1.2865x; 1.2295x over previous
#include <cuda_runtime.h>
#include <cuda_bf16.h>
#include <math.h>
#include <stdint.h>

#define BB    8
#define N1    2048
#define N2    8192
#define C1    256
#define C2    128
#define CIN   384
#define MOUT  256
#define NTOT  (BB*N2)      // 65536 columns
#define BNCOL 64           // GEMM block N
#define NBLK  (NTOT/BNCOL) // 1024 GEMM blocks

// pipeline geometry
#define PSTAGES   3
#define XROW      72                           // X row stride (words)
#define W_STAGE   (256*20*4)                   // 20480 B (one bulk copy)
#define X_STAGE   (16*XROW*4)                  // 4608 B
#define WOFF      0
#define XOFF      (PSTAGES*W_STAGE)            // 61440
#define SCOFF     (XOFF + PSTAGES*X_STAGE)     // 75264
#define MBOFF     (SCOFF + 2*256*4)            // 77312 (3 mbarriers)
#define SMEM_DYN  (MBOFF + 64)

#define WCH1 (CIN/16)   // 24 W chunks for GEMM1
#define WCH2 (MOUT/16)  // 16 W chunks for GEMM2

// ---------------- scratch (static __device__; no allocation) ----------------
__device__ int    g_idx[BB*N2*3];
__device__ float  g_wgt[BB*N2*3];
__device__ float  g_interp[(size_t)BB*C1*N2];   // 67 MB
__device__ float  g_Y1[(size_t)BB*MOUT*N2];     // 67 MB
__device__ float  g_scale1[MOUT], g_shift1[MOUT];
__device__ float  g_scale2[MOUT], g_shift2[MOUT];
__device__ float2 g_bpart[(size_t)NBLK*MOUT];   // per-block {sum,sumsq}
// pre-baked W smem images (bf16 hi/lo per 16-k chunk):
// row m = 40 uint16: [0..15]=hi bf16, [16..31]=lo bf16, [32..39]=pad
__device__ __align__(128) unsigned short g_W1img[WCH1*256*40];
__device__ __align__(128) unsigned short g_W2img[WCH2*256*40];

// ---------------- 1) three_nn ------------------------------------------------
__global__ void knn_kernel(const float* __restrict__ xyz2,
                           const float* __restrict__ xyz1)
{
    __shared__ float sx[N1], sy[N1], sz[N1];
    const int b = blockIdx.y;
    const float* p1 = xyz1 + (size_t)b * 3 * N1;
    for (int t = threadIdx.x; t < N1; t += blockDim.x) {
        sx[t] = p1[t];
        sy[t] = p1[N1 + t];
        sz[t] = p1[2*N1 + t];
    }
    __syncthreads();

    const int n = blockIdx.x * blockDim.x + threadIdx.x;
    const float* p2 = xyz2 + (size_t)b * 3 * N2;
    const float px = p2[n], py = p2[N2 + n], pz = p2[2*N2 + n];

    float d0 = 3.4e38f, d1 = 3.4e38f, d2v = 3.4e38f;
    int   i0 = 0, i1 = 0, i2 = 0;
    #pragma unroll 4
    for (int j = 0; j < N1; ++j) {
        float dx = px - sx[j];
        float dy = py - sy[j];
        float dz = pz - sz[j];
        float d = dx*dx + dy*dy + dz*dz;
        if (d < d2v) {
            if (d < d1) {
                d2v = d1; i2 = i1;
                if (d < d0) { d1 = d0; i1 = i0; d0 = d; i0 = j; }
                else        { d1 = d;  i1 = j; }
            } else { d2v = d; i2 = j; }
        }
    }
    d0  = fmaxf(d0,  1e-10f);
    d1  = fmaxf(d1,  1e-10f);
    d2v = fmaxf(d2v, 1e-10f);
    float r0 = 1.0f / d0, r1 = 1.0f / d1, r2 = 1.0f / d2v;
    float inv = 1.0f / (r0 + r1 + r2);
    size_t base = ((size_t)b * N2 + n) * 3;
    g_idx[base]   = i0; g_idx[base+1] = i1; g_idx[base+2] = i2;
    g_wgt[base]   = r0*inv; g_wgt[base+1] = r1*inv; g_wgt[base+2] = r2*inv;
}

// ---------------- 2) weighted gather -> g_interp ----------------------------
__global__ void interp_kernel(const float* __restrict__ feat1)
{
    const int b = blockIdx.y;
    const int n = blockIdx.x * blockDim.x + threadIdx.x;
    size_t base = ((size_t)b * N2 + n) * 3;
    const int   i0 = g_idx[base], i1 = g_idx[base+1], i2 = g_idx[base+2];
    const float w0 = g_wgt[base], w1 = g_wgt[base+1], w2 = g_wgt[base+2];
    const float* f1 = feat1 + (size_t)b * C1 * N1;
    float* X = g_interp + (size_t)b * C1 * N2 + n;
    #pragma unroll 4
    for (int c = 0; c < C1; ++c) {
        const float* row = f1 + c * N1;
        X[(size_t)c * N2] = w0 * row[i0] + w1 * row[i1] + w2 * row[i2];
    }
}

// ---------------- prep: W -> bf16 hi/lo chunk-major smem images -------------
__global__ void prep_wimg_kernel(const float* __restrict__ W1,
                                 const float* __restrict__ W2)
{
    const int idx = blockIdx.x * blockDim.x + threadIdx.x;  // one row (c,m)
    if (idx < WCH1*256) {
        const int c = idx / 256, m = idx % 256;
        unsigned short* row = g_W1img + (size_t)idx * 40;
        #pragma unroll
        for (int k = 0; k < 16; ++k) {
            float v = W1[(size_t)m * CIN + c*16 + k];
            __nv_bfloat16 h = __float2bfloat16(v);
            __nv_bfloat16 l = __float2bfloat16(v - __bfloat162float(h));
            row[k]      = *reinterpret_cast<unsigned short*>(&h);
            row[16 + k] = *reinterpret_cast<unsigned short*>(&l);
        }
        #pragma unroll
        for (int k = 32; k < 40; ++k) row[k] = 0;
    }
    if (idx < WCH2*256) {
        const int c = idx / 256, m = idx % 256;
        unsigned short* row = g_W2img + (size_t)idx * 40;
        #pragma unroll
        for (int k = 0; k < 16; ++k) {
            float v = W2[(size_t)m * MOUT + c*16 + k];
            __nv_bfloat16 h = __float2bfloat16(v);
            __nv_bfloat16 l = __float2bfloat16(v - __bfloat162float(h));
            row[k]      = *reinterpret_cast<unsigned short*>(&h);
            row[16 + k] = *reinterpret_cast<unsigned short*>(&l);
        }
        #pragma unroll
        for (int k = 32; k < 40; ++k) row[k] = 0;
    }
}

// ---------------- mma / ldmatrix / async wrappers ---------------------------
__device__ __forceinline__ void mma_bf16(float* d, const uint32_t* a, const uint32_t* b)
{
    asm volatile(
        "mma.sync.aligned.m16n8k16.row.col.f32.bf16.bf16.f32 "
        "{%0,%1,%2,%3}, {%4,%5,%6,%7}, {%8,%9}, {%0,%1,%2,%3};\n"
        : "+f"(d[0]), "+f"(d[1]), "+f"(d[2]), "+f"(d[3])
        : "r"(a[0]), "r"(a[1]), "r"(a[2]), "r"(a[3]),
          "r"(b[0]), "r"(b[1]));
}

__device__ __forceinline__ void ldsm_x4(uint32_t* r, uint32_t saddr)
{
    asm volatile(
        "ldmatrix.sync.aligned.m8n8.x4.shared.b16 {%0,%1,%2,%3}, [%4];\n"
        : "=r"(r[0]), "=r"(r[1]), "=r"(r[2]), "=r"(r[3])
        : "r"(saddr));
}

__device__ __forceinline__ uint32_t pack_bf16(float lo, float hi)
{
    uint32_t r;
    asm volatile("cvt.rn.bf16x2.f32 %0, %1, %2;" : "=r"(r) : "f"(hi), "f"(lo));
    return r;
}
__device__ __forceinline__ float bflo_f(uint32_t p) { return __uint_as_float(p << 16); }
__device__ __forceinline__ float bfhi_f(uint32_t p) { return __uint_as_float(p & 0xFFFF0000u); }

__device__ __forceinline__ void cp_async16(uint32_t dst, const void* src)
{
    asm volatile("cp.async.cg.shared.global [%0], [%1], 16;\n"
                 :: "r"(dst), "l"(src));
}
__device__ __forceinline__ void cp_commit()
{
    asm volatile("cp.async.commit_group;\n");
}
template<int N>
__device__ __forceinline__ void cp_wait()
{
    asm volatile("cp.async.wait_group %0;\n" :: "n"(N));
}
__device__ __forceinline__ void bulk_g2s(uint32_t dst, const void* src,
                                         uint32_t bytes, uint32_t mbar)
{
    asm volatile(
        "cp.async.bulk.shared::cluster.global.mbarrier::complete_tx::bytes "
        "[%0], [%1], %2, [%3];"
        :: "r"(dst), "l"(src), "r"(bytes), "r"(mbar) : "memory");
}
__device__ __forceinline__ void mbar_init(uint32_t mbar, uint32_t cnt)
{
    asm volatile("mbarrier.init.shared.b64 [%0], %1;" :: "r"(mbar), "r"(cnt) : "memory");
}
__device__ __forceinline__ void mbar_expect_tx(uint32_t mbar, uint32_t bytes)
{
    asm volatile("mbarrier.arrive.expect_tx.shared.b64 _, [%0], %1;"
                 :: "r"(mbar), "r"(bytes) : "memory");
}
__device__ __forceinline__ void mbar_wait(uint32_t mbar, uint32_t parity)
{
    asm volatile(
        "{\n\t.reg .pred P;\n\t"
        "W_%=:\n\t"
        "mbarrier.try_wait.parity.acquire.cta.shared::cta.b64 P, [%0], %1, 0x989680;\n\t"
        "@P bra D_%=;\n\t"
        "bra W_%=;\n\t"
        "D_%=:\n\t}"
        :: "r"(mbar), "r"(parity) : "memory");
}

// ---------------- 3/5) tensor-core GEMM, 3x bf16 k16, bulk-W + cp.async-X ---
// out[b,m,n2] = sum_k W[m,k]*X[k,(b,n2)] + bias[m]; Wimg = bf16 hi/lo images.
// CONCAT: X rows [0,C1) from A1 (g_interp), rest from A2 (feat2).
// FUSE:   X element -> relu(x*scale[k]+shift[k]) applied before bf16 split.
// Emits per-block per-channel {sum,sumsq} into bpart (fused BN stats).
template<int K, bool CONCAT, bool FUSE>
__global__ void __launch_bounds__(512, 2)
gemm_tc_kernel(const unsigned short* __restrict__ Wimg,
               const float* __restrict__ bias,
               const float* __restrict__ A1, const float* __restrict__ A2,
               const float* __restrict__ scale, const float* __restrict__ shift,
               float* __restrict__ out, float2* __restrict__ bpart)
{
    extern __shared__ char sm[];
    const uint32_t smb = (uint32_t)__cvta_generic_to_shared(sm);
    const uint32_t wsm = smb + WOFF;
    const uint32_t xsm = smb + XOFF;
    float* s_sc = (float*)(sm + SCOFF);
    float* s_sh = (float*)(sm + SCOFF + 256*4);
    const uint32_t mb0 = smb + MBOFF;   // 3 mbarriers, 8B apart

    const int tid   = threadIdx.x;
    const int lane  = tid & 31;
    const int wid   = tid >> 5;         // 0..15
    const int g     = lane >> 2;
    const int tig   = lane & 3;
    const int mwarp = wid >> 1;         // 0..7 -> m base mwarp*32
    const int nwarp = wid & 1;          // 0..1 -> n base nwarp*32

    const int nglob = blockIdx.x * BNCOL;
    const int b     = nglob >> 13;
    const int n2    = nglob & (N2 - 1);

    const float* A1b = A1 + (size_t)b * (CONCAT ? C1 : K) * N2 + n2;
    const float* A2b = CONCAT ? (A2 + (size_t)b * C2 * N2 + n2) : nullptr;

    if (FUSE && tid < K) {
        s_sc[tid] = scale[tid];
        s_sh[tid] = shift[tid];
    }
    if (tid == 0) {
        mbar_init(mb0,      1);
        mbar_init(mb0 + 8,  1);
        mbar_init(mb0 + 16, 1);
    }
    __syncthreads();   // mbarriers + s_sc visible

    float acc[2][4][4];
    #pragma unroll
    for (int mt = 0; mt < 2; ++mt)
        #pragma unroll
        for (int nt = 0; nt < 4; ++nt)
            #pragma unroll
            for (int r = 0; r < 4; ++r) acc[mt][nt][r] = 0.0f;

    // ldmatrix lane address within a W stage (row stride 80B)
    const int rowoff  = ((lane >> 3) & 1) * 8 + (lane & 7);
    const int wordoff = (lane >> 4) * 4;      // k-half: 0 or 16 bytes
    const uint32_t aOff = ((((mwarp*32 + rowoff) * 20) + wordoff) << 2);

    // X loader task coords (tid<256)
    const int xkr = tid >> 4;
    const int xn4 = (tid & 15) * 4;

    auto load_W = [&](int chunk, int stg) {        // tid==0 only
        mbar_expect_tx(mb0 + stg * 8, W_STAGE);
        bulk_g2s(wsm + stg * W_STAGE, Wimg + (size_t)chunk * (256*40),
                 W_STAGE, mb0 + stg * 8);
    };
    auto load_X = [&](int k0, int stg) {           // tid<256
        if (tid < 256) {
            const int kg = k0 + xkr;
            const float* src;
            if (CONCAT)
                src = (kg < C1) ? (A1b + (size_t)kg * N2)
                                : (A2b + (size_t)(kg - C1) * N2);
            else
                src = A1b + (size_t)kg * N2;
            cp_async16(xsm + stg * X_STAGE + (((xkr * XROW) + xn4) << 2),
                       src + xn4);
        }
    };

    constexpr int NITER = K / 16;
    #pragma unroll
    for (int p = 0; p < PSTAGES - 1; ++p) {
        if (tid == 0) load_W(p, p);
        load_X(p * 16, p);
        cp_commit();
    }

    int s = 0, ph = 0;
    for (int i = 0; i < NITER; ++i) {
        const int inext = i + PSTAGES - 1;
        const int sN = (s + PSTAGES - 1) % PSTAGES;
        if (inext < NITER) load_X(inext * 16, sN);
        cp_commit();
        cp_wait<PSTAGES - 2>();
        mbar_wait(mb0 + s * 8, (uint32_t)ph);
        __syncthreads();
        if (inext < NITER && tid == 0) load_W(inext, sN);

        const uint32_t aBase = wsm + s * W_STAGE + aOff;
        const float* Xs = (const float*)(sm + XOFF + s * X_STAGE);
        const int k0 = i * 16;

        // per-k scale/shift for the 4 k-rows this thread touches
        float sc0, sh0, sc1, sh1, sc2, sh2, sc3, sh3;
        if (FUSE) {
            sc0 = s_sc[k0 + 2*tig];     sh0 = s_sh[k0 + 2*tig];
            sc1 = s_sc[k0 + 2*tig + 1]; sh1 = s_sh[k0 + 2*tig + 1];
            sc2 = s_sc[k0 + 2*tig + 8]; sh2 = s_sh[k0 + 2*tig + 8];
            sc3 = s_sc[k0 + 2*tig + 9]; sh3 = s_sh[k0 + 2*tig + 9];
        }

        // build b-fragments once (hi + lo), reuse across both mt
        uint32_t bh[4][2], bl[4][2];
        #pragma unroll
        for (int nt = 0; nt < 4; ++nt) {
            const int nn = nwarp * 32 + nt * 8 + g;
            float x0 = Xs[(2*tig)     * XROW + nn];
            float x1 = Xs[(2*tig + 1) * XROW + nn];
            float x2 = Xs[(2*tig + 8) * XROW + nn];
            float x3 = Xs[(2*tig + 9) * XROW + nn];
            if (FUSE) {
                x0 = fmaxf(fmaf(x0, sc0, sh0), 0.0f);
                x1 = fmaxf(fmaf(x1, sc1, sh1), 0.0f);
                x2 = fmaxf(fmaf(x2, sc2, sh2), 0.0f);
                x3 = fmaxf(fmaf(x3, sc3, sh3), 0.0f);
            }
            const uint32_t h0 = pack_bf16(x0, x1);
            const uint32_t h1 = pack_bf16(x2, x3);
            bh[nt][0] = h0; bh[nt][1] = h1;
            bl[nt][0] = pack_bf16(x0 - bflo_f(h0), x1 - bfhi_f(h0));
            bl[nt][1] = pack_bf16(x2 - bflo_f(h1), x3 - bfhi_f(h1));
        }

        #pragma unroll
        for (int mt = 0; mt < 2; ++mt) {
            uint32_t ah[4], al[4];
            ldsm_x4(ah, aBase + mt * 1280);        // hi (bytes 0..31 of row)
            ldsm_x4(al, aBase + mt * 1280 + 32);   // lo (bytes 32..63)
            #pragma unroll
            for (int nt = 0; nt < 4; ++nt) {
                mma_bf16(acc[mt][nt], ah, bh[nt]);   // hi*hi
                mma_bf16(acc[mt][nt], ah, bl[nt]);   // hi*lo
                mma_bf16(acc[mt][nt], al, bh[nt]);   // lo*hi
            }
        }
        __syncthreads();
        if (++s == PSTAGES) { s = 0; ph ^= 1; }
    }

    // ---- epilogue: bias add, store, fused per-channel stats ----
    float* part = (float*)sm;   // reuse W stage 0: [nwarp][256][{s,ss}]
    float* ob = out + (size_t)b * MOUT * N2 + n2;
    #pragma unroll
    for (int mt = 0; mt < 2; ++mt) {
        #pragma unroll
        for (int h = 0; h < 2; ++h) {
            const int m  = mwarp * 32 + mt * 16 + h * 8 + g;
            const float bv = bias[m];
            float s2 = 0.0f, ss = 0.0f;
            #pragma unroll
            for (int nt = 0; nt < 4; ++nt) {
                const float v0 = acc[mt][nt][h*2+0] + bv;
                const float v1 = acc[mt][nt][h*2+1] + bv;
                const int n = nwarp * 32 + nt * 8 + 2 * tig;
                *(float2*)(ob + (size_t)m * N2 + n) = make_float2(v0, v1);
                s2 += v0 + v1;
                ss += v0*v0 + v1*v1;
            }
            s2 += __shfl_xor_sync(0xffffffffu, s2, 1);
            s2 += __shfl_xor_sync(0xffffffffu, s2, 2);
            ss += __shfl_xor_sync(0xffffffffu, ss, 1);
            ss += __shfl_xor_sync(0xffffffffu, ss, 2);
            if (tig == 0) {
                part[(nwarp * 256 + m) * 2 + 0] = s2;
                part[(nwarp * 256 + m) * 2 + 1] = ss;
            }
        }
    }
    __syncthreads();
    if (tid < 256) {
        float2 r;
        r.x = part[tid * 2]     + part[(256 + tid) * 2];
        r.y = part[tid * 2 + 1] + part[(256 + tid) * 2 + 1];
        bpart[(size_t)blockIdx.x * MOUT + tid] = r;
    }
}

// ---------------- 4/6) stage-2 stats reduce ---------------------------------
__global__ void stats2_kernel(const float* __restrict__ gamma,
                              const float* __restrict__ beta,
                              float* __restrict__ scale,
                              float* __restrict__ shift)
{
    const int c = blockIdx.x;
    double s = 0.0, ss = 0.0;
    for (int j = threadIdx.x; j < NBLK; j += 256) {
        const float2 p = g_bpart[(size_t)j * MOUT + c];
        s  += (double)p.x;
        ss += (double)p.y;
    }
    __shared__ double rs[256], rss[256];
    rs[threadIdx.x] = s; rss[threadIdx.x] = ss;
    __syncthreads();
    for (int o = 128; o > 0; o >>= 1) {
        if (threadIdx.x < o) {
            rs[threadIdx.x]  += rs[threadIdx.x + o];
            rss[threadIdx.x] += rss[threadIdx.x + o];
        }
        __syncthreads();
    }
    if (threadIdx.x == 0) {
        const double mean = rs[0] / (double)NTOT;
        const double var  = rss[0] / (double)NTOT - mean * mean;
        const float istd  = (float)(1.0 / sqrt(var + 1e-3));
        const float sc    = gamma[c] * istd;
        scale[c] = sc;
        shift[c] = beta[c] - (float)mean * sc;
    }
}

// ---------------- 7) in-place BN+ReLU of layer-2 output ---------------------
__global__ void finalize_kernel(float* __restrict__ out)
{
    const size_t i4 = (size_t)blockIdx.x * blockDim.x + threadIdx.x;
    const int c = (int)((i4 >> 11) & 255);
    float4* p = (float4*)out + i4;
    float4 v = *p;
    const float sc = g_scale2[c], sh = g_shift2[c];
    v.x = fmaxf(fmaf(v.x, sc, sh), 0.0f);
    v.y = fmaxf(fmaf(v.y, sc, sh), 0.0f);
    v.z = fmaxf(fmaf(v.z, sc, sh), 0.0f);
    v.w = fmaxf(fmaf(v.w, sc, sh), 0.0f);
    *p = v;
}

// ---------------- launch ----------------------------------------------------
extern "C" void kernel_launch(void* const* d_in, const int* in_sizes, int n_in,
                              void* d_out, int out_size)
{
    const float* xyz2  = (const float*)d_in[0];
    const float* xyz1  = (const float*)d_in[1];
    const float* feat2 = (const float*)d_in[2];
    const float* feat1 = (const float*)d_in[3];
    const float* W1    = (const float*)d_in[4];
    const float* b1    = (const float*)d_in[5];
    const float* g1    = (const float*)d_in[6];
    const float* be1   = (const float*)d_in[7];
    const float* W2    = (const float*)d_in[8];
    const float* b2    = (const float*)d_in[9];
    const float* g2    = (const float*)d_in[10];
    const float* be2   = (const float*)d_in[11];
    float* out = (float*)d_out;

    float  *p_interp, *p_Y1, *p_s1, *p_sh1, *p_s2, *p_sh2;
    unsigned short *p_W1img, *p_W2img;
    float2 *p_bpart;
    cudaGetSymbolAddress((void**)&p_interp, g_interp);
    cudaGetSymbolAddress((void**)&p_Y1,     g_Y1);
    cudaGetSymbolAddress((void**)&p_s1,     g_scale1);
    cudaGetSymbolAddress((void**)&p_sh1,    g_shift1);
    cudaGetSymbolAddress((void**)&p_s2,     g_scale2);
    cudaGetSymbolAddress((void**)&p_sh2,    g_shift2);
    cudaGetSymbolAddress((void**)&p_bpart,  g_bpart);
    cudaGetSymbolAddress((void**)&p_W1img,  g_W1img);
    cudaGetSymbolAddress((void**)&p_W2img,  g_W2img);

    static int attr_done = 0;
    if (!attr_done) {
        cudaFuncSetAttribute(gemm_tc_kernel<CIN, true, false>,
                             cudaFuncAttributeMaxDynamicSharedMemorySize, SMEM_DYN);
        cudaFuncSetAttribute(gemm_tc_kernel<MOUT, false, true>,
                             cudaFuncAttributeMaxDynamicSharedMemorySize, SMEM_DYN);
        attr_done = 1;
    }

    knn_kernel<<<dim3(N2/256, BB), 256>>>(xyz2, xyz1);
    interp_kernel<<<dim3(N2/256, BB), 256>>>(feat1);
    prep_wimg_kernel<<<(WCH1*256 + 255)/256, 256>>>(W1, W2);

    // layer 1: y1 = W1 @ [interp; feat2] + b1 (raw) + fused stats partials
    gemm_tc_kernel<CIN, true, false><<<NBLK, 512, SMEM_DYN>>>(
        p_W1img, b1, p_interp, feat2, nullptr, nullptr, p_Y1, p_bpart);
    stats2_kernel<<<MOUT, 256>>>(g1, be1, p_s1, p_sh1);

    // layer 2: y2 = W2 @ relu(bn(y1)) + b2 -> d_out (raw) + fused stats
    gemm_tc_kernel<MOUT, false, true><<<NBLK, 512, SMEM_DYN>>>(
        p_W2img, b2, p_Y1, nullptr, p_s1, p_sh1, out, p_bpart);
    stats2_kernel<<<MOUT, 256>>>(g2, be2, p_s2, p_sh2);

    finalize_kernel<<<(NTOT * MOUT / 4) / 256, 256>>>(out);
}

// round 11
// speedup vs baseline: 1.3017x; 1.0119x over previous
#include <cuda_runtime.h>
#include <cuda_bf16.h>
#include <math.h>
#include <stdint.h>

#define BB    8
#define N1    2048
#define N2    8192
#define C1    256
#define C2    128
#define CIN   384
#define MOUT  256
#define NTOT  (BB*N2)      // 65536 columns
#define BNCOL 64           // GEMM block N
#define NBLK  (NTOT/BNCOL) // 1024 GEMM blocks
#define KP1   (CIN/2)      // 192 kpairs (GEMM1)
#define KP2   (MOUT/2)     // 128 kpairs (GEMM2)

// pipeline geometry
#define PSTAGES   3
#define XROW      72                           // X row stride (u32)
#define W_STAGE   (256*20*4)                   // 20480 B (one bulk copy)
#define X_STAGE   (16*XROW*4)                  // 4608 B (8 hi rows + 8 lo rows)
#define WOFF      0
#define XOFF      (PSTAGES*W_STAGE)            // 61440
#define MBOFF     (XOFF + PSTAGES*X_STAGE)     // 75264 (3 mbarriers)
#define SMEM_DYN  (MBOFF + 64)

#define WCH1 (CIN/16)   // 24 W chunks for GEMM1
#define WCH2 (MOUT/16)  // 16 W chunks for GEMM2

// ---------------- scratch (static __device__; no allocation) ----------------
__device__ int    g_idx[BB*N2*3];
__device__ float  g_wgt[BB*N2*3];
__device__ float  g_Y1[(size_t)BB*MOUT*N2];     // 67 MB raw layer-1 out
__device__ float  g_scale1[MOUT], g_shift1[MOUT];
__device__ float  g_scale2[MOUT], g_shift2[MOUT];
__device__ float2 g_bpart[(size_t)NBLK*MOUT];   // per-block {sum,sumsq}
// packed X planes: u32 = (bf16(k_odd)<<16)|bf16(k_even), [b][kpair][n]
__device__ uint32_t g_X1h[(size_t)BB*KP1*N2];   // 50 MB
__device__ uint32_t g_X1l[(size_t)BB*KP1*N2];
__device__ uint32_t g_X2h[(size_t)BB*KP2*N2];   // 34 MB
__device__ uint32_t g_X2l[(size_t)BB*KP2*N2];
// pre-baked W smem images (bf16 hi/lo per 16-k chunk):
// row m = 40 uint16: [0..15]=hi bf16, [16..31]=lo bf16, [32..39]=pad
__device__ __align__(128) unsigned short g_W1img[WCH1*256*40];
__device__ __align__(128) unsigned short g_W2img[WCH2*256*40];

__device__ __forceinline__ uint32_t pack_bf16(float lo, float hi)
{
    uint32_t r;
    asm volatile("cvt.rn.bf16x2.f32 %0, %1, %2;" : "=r"(r) : "f"(hi), "f"(lo));
    return r;
}
__device__ __forceinline__ float bflo_f(uint32_t p) { return __uint_as_float(p << 16); }
__device__ __forceinline__ float bfhi_f(uint32_t p) { return __uint_as_float(p & 0xFFFF0000u); }

// ---------------- 1) three_nn ------------------------------------------------
__global__ void knn_kernel(const float* __restrict__ xyz2,
                           const float* __restrict__ xyz1)
{
    __shared__ float sx[N1], sy[N1], sz[N1];
    const int b = blockIdx.y;
    const float* p1 = xyz1 + (size_t)b * 3 * N1;
    for (int t = threadIdx.x; t < N1; t += blockDim.x) {
        sx[t] = p1[t];
        sy[t] = p1[N1 + t];
        sz[t] = p1[2*N1 + t];
    }
    __syncthreads();

    const int n = blockIdx.x * blockDim.x + threadIdx.x;
    const float* p2 = xyz2 + (size_t)b * 3 * N2;
    const float px = p2[n], py = p2[N2 + n], pz = p2[2*N2 + n];

    float d0 = 3.4e38f, d1 = 3.4e38f, d2v = 3.4e38f;
    int   i0 = 0, i1 = 0, i2 = 0;
    #pragma unroll 4
    for (int j = 0; j < N1; ++j) {
        float dx = px - sx[j];
        float dy = py - sy[j];
        float dz = pz - sz[j];
        float d = dx*dx + dy*dy + dz*dz;
        if (d < d2v) {
            if (d < d1) {
                d2v = d1; i2 = i1;
                if (d < d0) { d1 = d0; i1 = i0; d0 = d; i0 = j; }
                else        { d1 = d;  i1 = j; }
            } else { d2v = d; i2 = j; }
        }
    }
    d0  = fmaxf(d0,  1e-10f);
    d1  = fmaxf(d1,  1e-10f);
    d2v = fmaxf(d2v, 1e-10f);
    float r0 = 1.0f / d0, r1 = 1.0f / d1, r2 = 1.0f / d2v;
    float inv = 1.0f / (r0 + r1 + r2);
    size_t base = ((size_t)b * N2 + n) * 3;
    g_idx[base]   = i0; g_idx[base+1] = i1; g_idx[base+2] = i2;
    g_wgt[base]   = r0*inv; g_wgt[base+1] = r1*inv; g_wgt[base+2] = r2*inv;
}

// ---------------- 2) weighted gather -> packed X1 planes (kpair 0..127) -----
__global__ void interp_pack_kernel(const float* __restrict__ feat1)
{
    const int b = blockIdx.y;
    const int n = blockIdx.x * blockDim.x + threadIdx.x;
    size_t base = ((size_t)b * N2 + n) * 3;
    const int   i0 = g_idx[base], i1 = g_idx[base+1], i2 = g_idx[base+2];
    const float w0 = g_wgt[base], w1 = g_wgt[base+1], w2 = g_wgt[base+2];
    const float* f1 = feat1 + (size_t)b * C1 * N1;
    uint32_t* Xh = g_X1h + (size_t)b * KP1 * N2 + n;
    uint32_t* Xl = g_X1l + (size_t)b * KP1 * N2 + n;
    #pragma unroll 2
    for (int c2 = 0; c2 < C1/2; ++c2) {
        const float* r0 = f1 + (2*c2) * N1;
        const float* r1 = r0 + N1;
        const float v0 = w0 * r0[i0] + w1 * r0[i1] + w2 * r0[i2];
        const float v1 = w0 * r1[i0] + w1 * r1[i1] + w2 * r1[i2];
        const uint32_t h = pack_bf16(v0, v1);
        Xh[(size_t)c2 * N2] = h;
        Xl[(size_t)c2 * N2] = pack_bf16(v0 - bflo_f(h), v1 - bfhi_f(h));
    }
}

// ---------------- 2b) feat2 -> packed X1 planes (kpair 128..191) ------------
__global__ void convF2_kernel(const float* __restrict__ feat2)
{
    const int b  = blockIdx.z;
    const int j2 = blockIdx.y;                   // 0..63
    const int n  = blockIdx.x * blockDim.x + threadIdx.x;
    const float v0 = feat2[((size_t)b * C2 + 2*j2)     * N2 + n];
    const float v1 = feat2[((size_t)b * C2 + 2*j2 + 1) * N2 + n];
    const uint32_t h = pack_bf16(v0, v1);
    const size_t o = ((size_t)b * KP1 + C1/2 + j2) * N2 + n;
    g_X1h[o] = h;
    g_X1l[o] = pack_bf16(v0 - bflo_f(h), v1 - bfhi_f(h));
}

// ---------------- 5b) relu(bn(y1)) -> packed X2 planes ----------------------
__global__ void convY_kernel()
{
    const int b  = blockIdx.z;
    const int c2 = blockIdx.y;                   // 0..127
    const int n  = blockIdx.x * blockDim.x + threadIdx.x;
    const int k0 = 2*c2, k1 = 2*c2 + 1;
    float v0 = g_Y1[((size_t)b * MOUT + k0) * N2 + n];
    float v1 = g_Y1[((size_t)b * MOUT + k1) * N2 + n];
    v0 = fmaxf(fmaf(v0, g_scale1[k0], g_shift1[k0]), 0.0f);
    v1 = fmaxf(fmaf(v1, g_scale1[k1], g_shift1[k1]), 0.0f);
    const uint32_t h = pack_bf16(v0, v1);
    const size_t o = ((size_t)b * KP2 + c2) * N2 + n;
    g_X2h[o] = h;
    g_X2l[o] = pack_bf16(v0 - bflo_f(h), v1 - bfhi_f(h));
}

// ---------------- prep: W -> bf16 hi/lo chunk-major smem images -------------
__global__ void prep_wimg_kernel(const float* __restrict__ W1,
                                 const float* __restrict__ W2)
{
    const int idx = blockIdx.x * blockDim.x + threadIdx.x;  // one row (c,m)
    if (idx < WCH1*256) {
        const int c = idx / 256, m = idx % 256;
        unsigned short* row = g_W1img + (size_t)idx * 40;
        #pragma unroll
        for (int k = 0; k < 16; ++k) {
            float v = W1[(size_t)m * CIN + c*16 + k];
            __nv_bfloat16 h = __float2bfloat16(v);
            __nv_bfloat16 l = __float2bfloat16(v - __bfloat162float(h));
            row[k]      = *reinterpret_cast<unsigned short*>(&h);
            row[16 + k] = *reinterpret_cast<unsigned short*>(&l);
        }
        #pragma unroll
        for (int k = 32; k < 40; ++k) row[k] = 0;
    }
    if (idx < WCH2*256) {
        const int c = idx / 256, m = idx % 256;
        unsigned short* row = g_W2img + (size_t)idx * 40;
        #pragma unroll
        for (int k = 0; k < 16; ++k) {
            float v = W2[(size_t)m * MOUT + c*16 + k];
            __nv_bfloat16 h = __float2bfloat16(v);
            __nv_bfloat16 l = __float2bfloat16(v - __bfloat162float(h));
            row[k]      = *reinterpret_cast<unsigned short*>(&h);
            row[16 + k] = *reinterpret_cast<unsigned short*>(&l);
        }
        #pragma unroll
        for (int k = 32; k < 40; ++k) row[k] = 0;
    }
}

// ---------------- mma / ldmatrix / async wrappers ---------------------------
__device__ __forceinline__ void mma_bf16(float* d, const uint32_t* a, const uint32_t* b)
{
    asm volatile(
        "mma.sync.aligned.m16n8k16.row.col.f32.bf16.bf16.f32 "
        "{%0,%1,%2,%3}, {%4,%5,%6,%7}, {%8,%9}, {%0,%1,%2,%3};\n"
        : "+f"(d[0]), "+f"(d[1]), "+f"(d[2]), "+f"(d[3])
        : "r"(a[0]), "r"(a[1]), "r"(a[2]), "r"(a[3]),
          "r"(b[0]), "r"(b[1]));
}

__device__ __forceinline__ void ldsm_x4(uint32_t* r, uint32_t saddr)
{
    asm volatile(
        "ldmatrix.sync.aligned.m8n8.x4.shared.b16 {%0,%1,%2,%3}, [%4];\n"
        : "=r"(r[0]), "=r"(r[1]), "=r"(r[2]), "=r"(r[3])
        : "r"(saddr));
}

__device__ __forceinline__ void cp_async16(uint32_t dst, const void* src)
{
    asm volatile("cp.async.cg.shared.global [%0], [%1], 16;\n"
                 :: "r"(dst), "l"(src));
}
__device__ __forceinline__ void cp_commit()
{
    asm volatile("cp.async.commit_group;\n");
}
template<int N>
__device__ __forceinline__ void cp_wait()
{
    asm volatile("cp.async.wait_group %0;\n" :: "n"(N));
}
__device__ __forceinline__ void bulk_g2s(uint32_t dst, const void* src,
                                         uint32_t bytes, uint32_t mbar)
{
    asm volatile(
        "cp.async.bulk.shared::cluster.global.mbarrier::complete_tx::bytes "
        "[%0], [%1], %2, [%3];"
        :: "r"(dst), "l"(src), "r"(bytes), "r"(mbar) : "memory");
}
__device__ __forceinline__ void mbar_init(uint32_t mbar, uint32_t cnt)
{
    asm volatile("mbarrier.init.shared.b64 [%0], %1;" :: "r"(mbar), "r"(cnt) : "memory");
}
__device__ __forceinline__ void mbar_expect_tx(uint32_t mbar, uint32_t bytes)
{
    asm volatile("mbarrier.arrive.expect_tx.shared.b64 _, [%0], %1;"
                 :: "r"(mbar), "r"(bytes) : "memory");
}
__device__ __forceinline__ void mbar_wait(uint32_t mbar, uint32_t parity)
{
    asm volatile(
        "{\n\t.reg .pred P;\n\t"
        "W_%=:\n\t"
        "mbarrier.try_wait.parity.acquire.cta.shared::cta.b64 P, [%0], %1, 0x989680;\n\t"
        "@P bra D_%=;\n\t"
        "bra W_%=;\n\t"
        "D_%=:\n\t}"
        :: "r"(mbar), "r"(parity) : "memory");
}

// ---------------- 3/5) tensor-core GEMM, 3x bf16 k16, pre-packed X ----------
// out[b,m,n2] = sum_k W[m,k]*X[k,(b,n2)] + bias[m]
// Wimg = bf16 hi/lo smem images (bulk-loaded); Xh/Xl = packed u32 pair-planes.
// Emits per-block per-channel {sum,sumsq} into bpart (fused BN stats).
template<int K>
__global__ void __launch_bounds__(512, 2)
gemm_tc_kernel(const unsigned short* __restrict__ Wimg,
               const float* __restrict__ bias,
               const uint32_t* __restrict__ Xh, const uint32_t* __restrict__ Xl,
               float* __restrict__ out, float2* __restrict__ bpart)
{
    constexpr int KP = K / 2;
    extern __shared__ char sm[];
    const uint32_t smb = (uint32_t)__cvta_generic_to_shared(sm);
    const uint32_t wsm = smb + WOFF;
    const uint32_t xsm = smb + XOFF;
    const uint32_t mb0 = smb + MBOFF;   // 3 mbarriers, 8B apart

    const int tid   = threadIdx.x;
    const int lane  = tid & 31;
    const int wid   = tid >> 5;         // 0..15
    const int g     = lane >> 2;
    const int tig   = lane & 3;
    const int mwarp = wid >> 1;         // 0..7 -> m base mwarp*32
    const int nwarp = wid & 1;          // 0..1 -> n base nwarp*32

    const int nglob = blockIdx.x * BNCOL;
    const int b     = nglob >> 13;
    const int n2    = nglob & (N2 - 1);

    const uint32_t* Xhb = Xh + (size_t)b * KP * N2 + n2;
    const uint32_t* Xlb = Xl + (size_t)b * KP * N2 + n2;

    if (tid == 0) {
        mbar_init(mb0,      1);
        mbar_init(mb0 + 8,  1);
        mbar_init(mb0 + 16, 1);
    }
    __syncthreads();

    float acc[2][4][4];
    #pragma unroll
    for (int mt = 0; mt < 2; ++mt)
        #pragma unroll
        for (int nt = 0; nt < 4; ++nt)
            #pragma unroll
            for (int r = 0; r < 4; ++r) acc[mt][nt][r] = 0.0f;

    // ldmatrix lane address within a W stage (row stride 80B)
    const int rowoff  = ((lane >> 3) & 1) * 8 + (lane & 7);
    const int wordoff = (lane >> 4) * 4;
    const uint32_t aOff = ((((mwarp*32 + rowoff) * 20) + wordoff) << 2);

    auto load_W = [&](int chunk, int stg) {        // tid==0 only
        mbar_expect_tx(mb0 + stg * 8, W_STAGE);
        bulk_g2s(wsm + stg * W_STAGE, Wimg + (size_t)chunk * (256*40),
                 W_STAGE, mb0 + stg * 8);
    };
    // X tile per stage: 8 kpair rows x 64 u32, hi rows 0..7, lo rows 8..15
    auto load_X = [&](int kp0, int stg) {          // tid<256
        if (tid < 256) {
            const int plane = tid >> 7;            // 0=hi, 1=lo
            const int t2  = tid & 127;
            const int xkr = t2 >> 4;               // 0..7
            const int xn4 = (t2 & 15) * 4;         // u32 quad
            const uint32_t* src = (plane ? Xlb : Xhb) + (size_t)(kp0 + xkr) * N2 + xn4;
            cp_async16(xsm + stg * X_STAGE
                           + (((plane*8 + xkr) * XROW + xn4) << 2), src);
        }
    };

    constexpr int NITER = K / 16;
    #pragma unroll
    for (int p = 0; p < PSTAGES - 1; ++p) {
        if (tid == 0) load_W(p, p);
        load_X(p * 8, p);
        cp_commit();
    }

    int s = 0, ph = 0;
    for (int i = 0; i < NITER; ++i) {
        const int inext = i + PSTAGES - 1;
        const int sN = (s + PSTAGES - 1) % PSTAGES;
        if (inext < NITER) load_X(inext * 8, sN);
        cp_commit();
        cp_wait<PSTAGES - 2>();
        mbar_wait(mb0 + s * 8, (uint32_t)ph);
        __syncthreads();
        if (inext < NITER && tid == 0) load_W(inext, sN);

        const uint32_t aBase = wsm + s * W_STAGE + aOff;
        const uint32_t* Xs = (const uint32_t*)(sm + XOFF + s * X_STAGE);

        // b-fragments: direct packed loads, no conversion
        uint32_t bh[4][2], bl[4][2];
        #pragma unroll
        for (int nt = 0; nt < 4; ++nt) {
            const int nn = nwarp * 32 + nt * 8 + g;
            bh[nt][0] = Xs[tig * XROW + nn];
            bh[nt][1] = Xs[(tig + 4) * XROW + nn];
            bl[nt][0] = Xs[(8 + tig) * XROW + nn];
            bl[nt][1] = Xs[(8 + tig + 4) * XROW + nn];
        }

        #pragma unroll
        for (int mt = 0; mt < 2; ++mt) {
            uint32_t ah[4], al[4];
            ldsm_x4(ah, aBase + mt * 1280);        // hi (bytes 0..31 of row)
            ldsm_x4(al, aBase + mt * 1280 + 32);   // lo (bytes 32..63)
            #pragma unroll
            for (int nt = 0; nt < 4; ++nt) {
                mma_bf16(acc[mt][nt], ah, bh[nt]);   // hi*hi
                mma_bf16(acc[mt][nt], ah, bl[nt]);   // hi*lo
                mma_bf16(acc[mt][nt], al, bh[nt]);   // lo*hi
            }
        }
        __syncthreads();
        if (++s == PSTAGES) { s = 0; ph ^= 1; }
    }

    // ---- epilogue: bias add, store, fused per-channel stats ----
    float* part = (float*)sm;   // reuse W stage 0: [nwarp][256][{s,ss}]
    float* ob = out + (size_t)b * MOUT * N2 + n2;
    #pragma unroll
    for (int mt = 0; mt < 2; ++mt) {
        #pragma unroll
        for (int h = 0; h < 2; ++h) {
            const int m  = mwarp * 32 + mt * 16 + h * 8 + g;
            const float bv = bias[m];
            float s2 = 0.0f, ss = 0.0f;
            #pragma unroll
            for (int nt = 0; nt < 4; ++nt) {
                const float v0 = acc[mt][nt][h*2+0] + bv;
                const float v1 = acc[mt][nt][h*2+1] + bv;
                const int n = nwarp * 32 + nt * 8 + 2 * tig;
                *(float2*)(ob + (size_t)m * N2 + n) = make_float2(v0, v1);
                s2 += v0 + v1;
                ss += v0*v0 + v1*v1;
            }
            s2 += __shfl_xor_sync(0xffffffffu, s2, 1);
            s2 += __shfl_xor_sync(0xffffffffu, s2, 2);
            ss += __shfl_xor_sync(0xffffffffu, ss, 1);
            ss += __shfl_xor_sync(0xffffffffu, ss, 2);
            if (tig == 0) {
                part[(nwarp * 256 + m) * 2 + 0] = s2;
                part[(nwarp * 256 + m) * 2 + 1] = ss;
            }
        }
    }
    __syncthreads();
    if (tid < 256) {
        float2 r;
        r.x = part[tid * 2]     + part[(256 + tid) * 2];
        r.y = part[tid * 2 + 1] + part[(256 + tid) * 2 + 1];
        bpart[(size_t)blockIdx.x * MOUT + tid] = r;
    }
}

// ---------------- 4/6) stage-2 stats reduce ---------------------------------
__global__ void stats2_kernel(const float* __restrict__ gamma,
                              const float* __restrict__ beta,
                              float* __restrict__ scale,
                              float* __restrict__ shift)
{
    const int c = blockIdx.x;
    double s = 0.0, ss = 0.0;
    for (int j = threadIdx.x; j < NBLK; j += 256) {
        const float2 p = g_bpart[(size_t)j * MOUT + c];
        s  += (double)p.x;
        ss += (double)p.y;
    }
    __shared__ double rs[256], rss[256];
    rs[threadIdx.x] = s; rss[threadIdx.x] = ss;
    __syncthreads();
    for (int o = 128; o > 0; o >>= 1) {
        if (threadIdx.x < o) {
            rs[threadIdx.x]  += rs[threadIdx.x + o];
            rss[threadIdx.x] += rss[threadIdx.x + o];
        }
        __syncthreads();
    }
    if (threadIdx.x == 0) {
        const double mean = rs[0] / (double)NTOT;
        const double var  = rss[0] / (double)NTOT - mean * mean;
        const float istd  = (float)(1.0 / sqrt(var + 1e-3));
        const float sc    = gamma[c] * istd;
        scale[c] = sc;
        shift[c] = beta[c] - (float)mean * sc;
    }
}

// ---------------- 7) in-place BN+ReLU of layer-2 output ---------------------
__global__ void finalize_kernel(float* __restrict__ out)
{
    const size_t i4 = (size_t)blockIdx.x * blockDim.x + threadIdx.x;
    const int c = (int)((i4 >> 11) & 255);
    float4* p = (float4*)out + i4;
    float4 v = *p;
    const float sc = g_scale2[c], sh = g_shift2[c];
    v.x = fmaxf(fmaf(v.x, sc, sh), 0.0f);
    v.y = fmaxf(fmaf(v.y, sc, sh), 0.0f);
    v.z = fmaxf(fmaf(v.z, sc, sh), 0.0f);
    v.w = fmaxf(fmaf(v.w, sc, sh), 0.0f);
    *p = v;
}

// ---------------- launch ----------------------------------------------------
extern "C" void kernel_launch(void* const* d_in, const int* in_sizes, int n_in,
                              void* d_out, int out_size)
{
    const float* xyz2  = (const float*)d_in[0];
    const float* xyz1  = (const float*)d_in[1];
    const float* feat2 = (const float*)d_in[2];
    const float* feat1 = (const float*)d_in[3];
    const float* W1    = (const float*)d_in[4];
    const float* b1    = (const float*)d_in[5];
    const float* g1    = (const float*)d_in[6];
    const float* be1   = (const float*)d_in[7];
    const float* W2    = (const float*)d_in[8];
    const float* b2    = (const float*)d_in[9];
    const float* g2    = (const float*)d_in[10];
    const float* be2   = (const float*)d_in[11];
    float* out = (float*)d_out;

    float  *p_Y1, *p_s1, *p_sh1, *p_s2, *p_sh2;
    unsigned short *p_W1img, *p_W2img;
    uint32_t *p_X1h, *p_X1l, *p_X2h, *p_X2l;
    float2 *p_bpart;
    cudaGetSymbolAddress((void**)&p_Y1,     g_Y1);
    cudaGetSymbolAddress((void**)&p_s1,     g_scale1);
    cudaGetSymbolAddress((void**)&p_sh1,    g_shift1);
    cudaGetSymbolAddress((void**)&p_s2,     g_scale2);
    cudaGetSymbolAddress((void**)&p_sh2,    g_shift2);
    cudaGetSymbolAddress((void**)&p_bpart,  g_bpart);
    cudaGetSymbolAddress((void**)&p_W1img,  g_W1img);
    cudaGetSymbolAddress((void**)&p_W2img,  g_W2img);
    cudaGetSymbolAddress((void**)&p_X1h,    g_X1h);
    cudaGetSymbolAddress((void**)&p_X1l,    g_X1l);
    cudaGetSymbolAddress((void**)&p_X2h,    g_X2h);
    cudaGetSymbolAddress((void**)&p_X2l,    g_X2l);

    static int attr_done = 0;
    if (!attr_done) {
        cudaFuncSetAttribute(gemm_tc_kernel<CIN>,
                             cudaFuncAttributeMaxDynamicSharedMemorySize, SMEM_DYN);
        cudaFuncSetAttribute(gemm_tc_kernel<MOUT>,
                             cudaFuncAttributeMaxDynamicSharedMemorySize, SMEM_DYN);
        attr_done = 1;
    }

    knn_kernel<<<dim3(N2/256, BB), 256>>>(xyz2, xyz1);
    interp_pack_kernel<<<dim3(N2/256, BB), 256>>>(feat1);
    convF2_kernel<<<dim3(N2/256, C2/2, BB), 256>>>(feat2);
    prep_wimg_kernel<<<(WCH1*256 + 255)/256, 256>>>(W1, W2);

    // layer 1: y1 = W1 @ [interp; feat2] + b1 (raw) + fused stats partials
    gemm_tc_kernel<CIN><<<NBLK, 512, SMEM_DYN>>>(
        p_W1img, b1, p_X1h, p_X1l, p_Y1, p_bpart);
    stats2_kernel<<<MOUT, 256>>>(g1, be1, p_s1, p_sh1);

    convY_kernel<<<dim3(N2/256, MOUT/2, BB), 256>>>();

    // layer 2: y2 = W2 @ relu(bn(y1)) + b2 -> d_out (raw) + fused stats
    gemm_tc_kernel<MOUT><<<NBLK, 512, SMEM_DYN>>>(
        p_W2img, b2, p_X2h, p_X2l, out, p_bpart);
    stats2_kernel<<<MOUT, 256>>>(g2, be2, p_s2, p_sh2);

    finalize_kernel<<<(NTOT * MOUT / 4) / 256, 256>>>(out);
}